// round 14
// baseline (speedup 1.0000x reference)
#include <cuda_runtime.h>
#include <cuda_fp16.h>
#include <stdint.h>

constexpr int CB = 16, CT = 2048, CN = 2048, CD = 128;
constexpr int BT = 128, BN = 64;
constexpr int NTILES = CN / BN;
constexpr float LOG2E = 1.4426950408889634f;
constexpr float LN2   = 0.6931471805599453f;

// Scratch (device globals — no allocation allowed)
__device__ float g_a2[CB * CN];     // a2 * LOG2E
__device__ float g_sbs[CB * CN];    // per-row int8 scale of sem
__device__ float g_m [CB * CT];
__device__ float g_M [CB];
__device__ float g_Z [CB];
__device__ __align__(16) float g_h2 [CB * CD];
__device__ __align__(16) float g_h2p[CB * 64 * CD];
__device__ __align__(16) __half g_sh[CB * CN * CD];   // fp16(sem)  (V)
__device__ __align__(16) char   g_s8[CB * CN * CD];   // int8(sem)  (B)

// ---------------- smem layout (bytes) ----------------
constexpr int OFF_A2S  = 0;                      // [2][64] f
constexpr int OFF_SBS  = 512;                    // [2][64] f
constexpr int OFF_MSA  = 1024;                   // [128] f  (A row scale * LOG2E)
constexpr int OFF_MSE  = 1536;                   // [128] f  (m staging)
constexpr int OFF_AS8  = 4096;                   // s8 [128][144] -> 18432
constexpr int OFF_BS8  = OFF_AS8 + 18432;        // 2 x s8 [64][144] -> 9216 each
constexpr int BBS8     = 9216;
constexpr int OFF_V    = OFF_BS8 + 2 * BBS8;     // 2 x f16 [64][136] stride 272
constexpr int VBUF     = 17408;
constexpr int SMEM_SZ  = OFF_V + 2 * VBUF;       // 75776 -> 2 CTAs/SM
constexpr int OFF_HS   = OFF_AS8;                // epilogue float hs[128][132]

__device__ __forceinline__ uint32_t smem_u32(const void* p) {
    uint32_t a;
    asm("{ .reg .u64 t; cvta.to.shared.u64 t, %1; cvt.u32.u64 %0, t; }" : "=r"(a) : "l"(p));
    return a;
}
__device__ __forceinline__ void ldsm4(uint32_t* r, uint32_t a) {
    asm volatile("ldmatrix.sync.aligned.m8n8.x4.shared.b16 {%0,%1,%2,%3}, [%4];"
                 : "=r"(r[0]), "=r"(r[1]), "=r"(r[2]), "=r"(r[3]) : "r"(a));
}
__device__ __forceinline__ void ldsm4t(uint32_t* r, uint32_t a) {
    asm volatile("ldmatrix.sync.aligned.m8n8.x4.trans.shared.b16 {%0,%1,%2,%3}, [%4];"
                 : "=r"(r[0]), "=r"(r[1]), "=r"(r[2]), "=r"(r[3]) : "r"(a));
}
__device__ __forceinline__ void mma16816h(uint32_t* c, const uint32_t* a, const uint32_t* b) {
    asm volatile(
        "mma.sync.aligned.m16n8k16.row.col.f16.f16.f16.f16 "
        "{%0,%1}, {%2,%3,%4,%5}, {%6,%7}, {%0,%1};"
        : "+r"(c[0]), "+r"(c[1])
        : "r"(a[0]), "r"(a[1]), "r"(a[2]), "r"(a[3]), "r"(b[0]), "r"(b[1]));
}
__device__ __forceinline__ void mma16832s8(int32_t* c, const uint32_t* a, const uint32_t* b) {
    asm volatile(
        "mma.sync.aligned.m16n8k32.row.col.s32.s8.s8.s32 "
        "{%0,%1,%2,%3}, {%4,%5,%6,%7}, {%8,%9}, {%0,%1,%2,%3};"
        : "+r"(c[0]), "+r"(c[1]), "+r"(c[2]), "+r"(c[3])
        : "r"(a[0]), "r"(a[1]), "r"(a[2]), "r"(a[3]), "r"(b[0]), "r"(b[1]));
}
__device__ __forceinline__ float ex2(float x) {
    float r;
    asm("ex2.approx.ftz.f32 %0, %1;" : "=f"(r) : "f"(x));
    return r;
}
__device__ __forceinline__ uint32_t packhf(float lo, float hi) {
    uint32_t r;
    asm("cvt.rn.f16x2.f32 %0, %1, %2;" : "=r"(r) : "f"(hi), "f"(lo));
    return r;
}
__device__ __forceinline__ float2 unpackh(uint32_t u) {
    __half2 h = *reinterpret_cast<__half2*>(&u);
    return __half22float2(h);
}
__device__ __forceinline__ void cpasync16(uint32_t saddr, const void* gaddr) {
    asm volatile("cp.async.cg.shared.global [%0], [%1], 16;" :: "r"(saddr), "l"(gaddr) : "memory");
}
__device__ __forceinline__ void cpasync_commit() {
    asm volatile("cp.async.commit_group;" ::: "memory");
}
template <int N>
__device__ __forceinline__ void cpasync_wait() {
    asm volatile("cp.async.wait_group %0;" :: "n"(N) : "memory");
}
__device__ __forceinline__ uint2 to_hf4(float4 v) {
    return make_uint2(packhf(v.x, v.y), packhf(v.z, v.w));
}
__device__ __forceinline__ uint32_t pack_s8(float4 v, float inv) {
    int q0 = __float2int_rn(v.x * inv), q1 = __float2int_rn(v.y * inv);
    int q2 = __float2int_rn(v.z * inv), q3 = __float2int_rn(v.w * inv);
    return (q0 & 255) | ((q1 & 255) << 8) | ((q2 & 255) << 16) | ((q3 & 255) << 24);
}

// ---------------------------------------------------------------------------
// K0: sem convert+prep: g_sh = fp16(sem); g_s8 = int8(sem) per-row scaled;
//     g_sbs = scale; g_a2 = (sem.w2)*LOG2E.   One warp per row.
// ---------------------------------------------------------------------------
__global__ void conv_kernel(const float* __restrict__ sem, const float* __restrict__ W) {
    int row = (blockIdx.x * blockDim.x + threadIdx.x) >> 5;
    int lane = threadIdx.x & 31;
    const float4* f  = reinterpret_cast<const float4*>(sem) + (size_t)row * 32;
    const float4* W4 = reinterpret_cast<const float4*>(W);
    float4 x  = f[lane];
    float4 wv = W4[32 + lane];
    float s = x.x * wv.x + x.y * wv.y + x.z * wv.z + x.w * wv.w;
    float mx = fmaxf(fmaxf(fabsf(x.x), fabsf(x.y)), fmaxf(fabsf(x.z), fabsf(x.w)));
    #pragma unroll
    for (int o = 16; o > 0; o >>= 1) {
        s += __shfl_xor_sync(0xffffffffu, s, o);
        mx = fmaxf(mx, __shfl_xor_sync(0xffffffffu, mx, o));
    }
    mx = fmaxf(mx, 1e-20f);
    float inv = 127.0f / mx;
    if (lane == 0) {
        g_a2[row]  = s * LOG2E;
        g_sbs[row] = mx * (1.0f / 127.0f);
    }
    reinterpret_cast<uint2*>(g_sh)[(size_t)row * 32 + lane] = to_hf4(x);
    reinterpret_cast<uint32_t*>(g_s8)[(size_t)row * 32 + lane] = pack_s8(x, inv);
}

// ---------------------------------------------------------------------------
// K1: register-P flash kernel. GEMM1 int8 (m16n8k32), GEMM2 fp16.
// 4 warps x 32 rows, 2 CTAs/SM.
// ---------------------------------------------------------------------------
__global__ void __launch_bounds__(128, 2)
flow_mma(const float* __restrict__ aud, const float* __restrict__ W,
         float* __restrict__ out) {
    extern __shared__ char smem[];
    const uint32_t sb = smem_u32(smem);
    const int tid = threadIdx.x, lane = tid & 31, w = tid >> 5;   // w in 0..3
    const int q = lane >> 2, cp = lane & 3;
    const int b = blockIdx.y, t0 = blockIdx.x * BT;

    float* a2s = (float*)(smem + OFF_A2S);
    float* sbs = (float*)(smem + OFF_SBS);
    float* msA = (float*)(smem + OFF_MSA);
    float* mse = (float*)(smem + OFF_MSE);

    const float* audb = aud + (size_t)(b * CT + t0) * CD;
    const char* gs80  = g_s8 + (size_t)(b * CN) * CD;
    const char* gsh0  = (const char*)(g_sh + (size_t)(b * CN) * CD);

    const int prow = tid & 63;
    const int pchB = (tid >> 6) * 64;    // int8 B: 2x 64B halves
    const int pchV = (tid >> 6) * 128;   // fp16 V: 2x 128B halves

    // ---- prologue: cp.async (B_s8 + V) tiles 0 and 1 ----
    #pragma unroll
    for (int cc = 0; cc < 4; cc++)
        cpasync16(sb + OFF_BS8 + prow * 144 + pchB + cc * 16,
                  gs80 + (size_t)prow * 128 + pchB + cc * 16);
    #pragma unroll
    for (int cc = 0; cc < 8; cc++)
        cpasync16(sb + OFF_V + prow * 272 + pchV + cc * 16,
                  gsh0 + (size_t)prow * 256 + pchV + cc * 16);
    cpasync_commit();
    #pragma unroll
    for (int cc = 0; cc < 4; cc++)
        cpasync16(sb + OFF_BS8 + BBS8 + prow * 144 + pchB + cc * 16,
                  gs80 + (size_t)(BN + prow) * 128 + pchB + cc * 16);
    #pragma unroll
    for (int cc = 0; cc < 8; cc++)
        cpasync16(sb + OFF_V + VBUF + prow * 272 + pchV + cc * 16,
                  gsh0 + (size_t)(BN + prow) * 256 + pchV + cc * 16);
    cpasync_commit();

    // ---- A = int8(aud*w3) per-row, built inline (own row) ----
    {
        int row = tid;
        float mx = 0.f;
        #pragma unroll
        for (int cc = 0; cc < 32; cc++) {
            int col = cc * 4;
            float4 v  = *reinterpret_cast<const float4*>(audb + (size_t)row * CD + col);
            float4 wq = *reinterpret_cast<const float4*>(W + 2 * CD + col);
            v.x *= wq.x; v.y *= wq.y; v.z *= wq.z; v.w *= wq.w;
            mx = fmaxf(mx, fmaxf(fmaxf(fabsf(v.x), fabsf(v.y)), fmaxf(fabsf(v.z), fabsf(v.w))));
        }
        mx = fmaxf(mx, 1e-20f);
        float inv = 127.0f / mx;
        #pragma unroll
        for (int cc = 0; cc < 32; cc++) {
            int col = cc * 4;
            float4 v  = *reinterpret_cast<const float4*>(audb + (size_t)row * CD + col);
            float4 wq = *reinterpret_cast<const float4*>(W + 2 * CD + col);
            v.x *= wq.x; v.y *= wq.y; v.z *= wq.z; v.w *= wq.w;
            *(uint32_t*)(smem + OFF_AS8 + row * 144 + col) = pack_s8(v, inv);
        }
        msA[row] = mx * (1.0f / 127.0f) * LOG2E;
        if (tid < 64) {
            a2s[tid] = g_a2[b * CN + tid];
            sbs[tid] = g_sbs[b * CN + tid];
        }
    }
    cpasync_wait<1>();       // tile 0 landed
    __syncthreads();

    // per-thread row scales (constant over tiles)
    float lsA[2][2];
    #pragma unroll
    for (int mi = 0; mi < 2; mi++) {
        lsA[mi][0] = msA[w * 32 + mi * 16 + q];
        lsA[mi][1] = msA[w * 32 + mi * 16 + q + 8];
    }

    const uint32_t aBase = sb + OFF_AS8 + (w * 32 + (lane & 15)) * 144 + (lane >> 4) * 16;

    uint32_t Oh[2][16][2];
    #pragma unroll
    for (int mi = 0; mi < 2; mi++)
        #pragma unroll
        for (int d = 0; d < 16; d++) { Oh[mi][d][0] = 0u; Oh[mi][d][1] = 0u; }
    float lreg[2][2] = {{0.f, 0.f}, {0.f, 0.f}};
    float mreg[2][2] = {{-1e30f, -1e30f}, {-1e30f, -1e30f}};

    for (int it = 0; it < NTILES; it++) {
        const int cur = it & 1, nxt = cur ^ 1;
        const uint32_t bBs8 = sb + OFF_BS8 + cur * BBS8;
        const uint32_t bV   = sb + OFF_V   + cur * VBUF;

        // ---- GEMM1: S[32,64] = A @ B^T  (int8, s32 accumulate) ----
        int32_t sacc[2][8][4];
        #pragma unroll
        for (int mi = 0; mi < 2; mi++)
            #pragma unroll
            for (int ni = 0; ni < 8; ni++)
                #pragma unroll
                for (int c = 0; c < 4; c++) sacc[mi][ni][c] = 0;

        #pragma unroll
        for (int kk = 0; kk < 4; kk++) {      // k32 steps
            uint32_t Afr[2][4];
            ldsm4(Afr[0], aBase + kk * 32);
            ldsm4(Afr[1], aBase + 16 * 144 + kk * 32);
            #pragma unroll
            for (int nn = 0; nn < 4; nn++) {
                uint32_t Bh[4];
                ldsm4(Bh, bBs8 + (nn * 16 + (lane & 7) + ((lane >> 4) & 1) * 8) * 144
                          + kk * 32 + ((lane >> 3) & 1) * 16);
                #pragma unroll
                for (int mi = 0; mi < 2; mi++) {
                    mma16832s8(sacc[mi][nn * 2 + 0], Afr[mi], Bh + 0);
                    mma16832s8(sacc[mi][nn * 2 + 1], Afr[mi], Bh + 2);
                }
            }
        }

        // ---- softmax: g = s32*(lsA*sB) + a2l ; P -> fp16 A-fragments ----
        uint32_t Pf[4][2][4];
        #pragma unroll
        for (int j = 0; j < 4; j++) {
            #pragma unroll
            for (int s = 0; s < 2; s++) {
                int ni = 2 * j + s;
                int col = ni * 8 + 2 * cp;
                float a20 = a2s[cur * 64 + col], a21 = a2s[cur * 64 + col + 1];
                float sb0 = sbs[cur * 64 + col], sb1 = sbs[cur * 64 + col + 1];
                #pragma unroll
                for (int mi = 0; mi < 2; mi++) {
                    float g0 = fmaf((float)sacc[mi][ni][0], lsA[mi][0] * sb0, a20);
                    float g1 = fmaf((float)sacc[mi][ni][1], lsA[mi][0] * sb1, a21);
                    float g2 = fmaf((float)sacc[mi][ni][2], lsA[mi][1] * sb0, a20);
                    float g3 = fmaf((float)sacc[mi][ni][3], lsA[mi][1] * sb1, a21);
                    float p0 = ex2(g0), p1 = ex2(g1), p2 = ex2(g2), p3 = ex2(g3);
                    mreg[mi][0] = fmaxf(mreg[mi][0], fmaxf(g0, g1));
                    mreg[mi][1] = fmaxf(mreg[mi][1], fmaxf(g2, g3));
                    lreg[mi][0] += p0 + p1;
                    lreg[mi][1] += p2 + p3;
                    Pf[j][mi][s * 2 + 0] = packhf(p0, p1);
                    Pf[j][mi][s * 2 + 1] = packhf(p2, p3);
                }
            }
        }

        // ---- tile it+1 resident (thread-local); a2/sbs for it+1 ----
        cpasync_wait<0>();
        if (it + 1 < NTILES && tid < 64) {
            a2s[nxt * 64 + tid] = g_a2[b * CN + (it + 1) * BN + tid];
            sbs[nxt * 64 + tid] = g_sbs[b * CN + (it + 1) * BN + tid];
        }

        // ---- GEMM2: O[32,128] += P @ V  (fp16) ----
        #pragma unroll
        for (int j = 0; j < 4; j++) {
            #pragma unroll
            for (int dd = 0; dd < 8; dd++) {
                uint32_t Vh[4];
                ldsm4t(Vh, bV + (j * 16 + (lane & 7) + ((lane >> 3) & 1) * 8) * 272
                           + (dd * 16 + (lane >> 4) * 8) * 2);
                #pragma unroll
                for (int mi = 0; mi < 2; mi++) {
                    mma16816h(Oh[mi][dd * 2 + 0], Pf[j][mi], Vh + 0);
                    mma16816h(Oh[mi][dd * 2 + 1], Pf[j][mi], Vh + 2);
                }
            }
        }
        __syncthreads();   // cur buffers free for refill; nxt visible CTA-wide

        // ---- fetch tile it+2 into cur buffers ----
        if (it + 2 < NTILES) {
            const char* gs = gs80 + (size_t)((it + 2) * BN + prow) * 128;
            const char* gv = gsh0 + (size_t)((it + 2) * BN + prow) * 256;
            #pragma unroll
            for (int cc = 0; cc < 4; cc++)
                cpasync16(sb + OFF_BS8 + cur * BBS8 + prow * 144 + pchB + cc * 16,
                          gs + pchB + cc * 16);
            #pragma unroll
            for (int cc = 0; cc < 8; cc++)
                cpasync16(sb + OFF_V + cur * VBUF + prow * 272 + pchV + cc * 16,
                          gv + pchV + cc * 16);
            cpasync_commit();
        }
    }

    // ---- l/m: warp-local; stage m'*ln2 in smem ----
    float inv2[2][2];
    #pragma unroll
    for (int mi = 0; mi < 2; mi++)
        #pragma unroll
        for (int half = 0; half < 2; half++) {
            float ls = lreg[mi][half], lm = mreg[mi][half];
            ls += __shfl_xor_sync(0xffffffffu, ls, 1);
            ls += __shfl_xor_sync(0xffffffffu, ls, 2);
            lm = fmaxf(lm, __shfl_xor_sync(0xffffffffu, lm, 1));
            lm = fmaxf(lm, __shfl_xor_sync(0xffffffffu, lm, 2));
            inv2[mi][half] = 1.0f / ls;
            if (cp == 0) mse[w * 32 + mi * 16 + q + half * 8] = lm * LN2;
        }
    __syncthreads();   // smem reads done; reuse as hs

    // ---- epilogue: h = O * (1/l), stage in smem, coalesced writes ----
    float* hs = (float*)(smem + OFF_HS);
    #pragma unroll
    for (int mi = 0; mi < 2; mi++)
        #pragma unroll
        for (int d2 = 0; d2 < 16; d2++) {
            int col = d2 * 8 + 2 * cp;
            int row0 = w * 32 + mi * 16 + q;
            float2 o01 = unpackh(Oh[mi][d2][0]);
            float2 o23 = unpackh(Oh[mi][d2][1]);
            *reinterpret_cast<float2*>(&hs[row0 * 132 + col]) =
                make_float2(o01.x * inv2[mi][0], o01.y * inv2[mi][0]);
            *reinterpret_cast<float2*>(&hs[(row0 + 8) * 132 + col]) =
                make_float2(o23.x * inv2[mi][1], o23.y * inv2[mi][1]);
        }
    __syncthreads();

    float4 wq1 = reinterpret_cast<const float4*>(W)[lane];
    #pragma unroll
    for (int e = 0; e < 32; e++) {
        int r = w + 4 * e;
        float4 a = reinterpret_cast<const float4*>(audb + (size_t)r * CD)[lane];
        float4 h = *reinterpret_cast<const float4*>(&hs[r * 132 + lane * 4]);
        float* orow = out + (size_t)(b * CT + t0 + r) * (4 * CD);
        reinterpret_cast<float4*>(orow)[lane] = a;
        reinterpret_cast<float4*>(orow + 128)[lane] = h;
        float4 m4 = make_float4(a.x * h.x, a.y * h.y, a.z * h.z, a.w * h.w);
        reinterpret_cast<float4*>(orow + 256)[lane] = m4;
        float part = a.x * wq1.x + a.y * wq1.y + a.z * wq1.z + a.w * wq1.w;
        #pragma unroll
        for (int o = 16; o > 0; o >>= 1) part += __shfl_xor_sync(0xffffffffu, part, o);
        if (lane == 0) g_m[b * CT + t0 + r] = mse[r] + part;
    }
}

// ---------------------------------------------------------------------------
// K2a: per batch: M = max_t m, Z = sum exp(m-M)
// ---------------------------------------------------------------------------
__global__ void bw_pre() {
    int b = blockIdx.x, tid = threadIdx.x;
    __shared__ float red[256];
    const float* mb = g_m + b * CT;
    float lm = -1e30f;
    for (int t = tid; t < CT; t += 256) lm = fmaxf(lm, mb[t]);
    red[tid] = lm; __syncthreads();
    for (int s = 128; s > 0; s >>= 1) { if (tid < s) red[tid] = fmaxf(red[tid], red[tid + s]); __syncthreads(); }
    float M = red[0]; __syncthreads();
    float ls = 0.f;
    for (int t = tid; t < CT; t += 256) ls += __expf(mb[t] - M);
    red[tid] = ls; __syncthreads();
    for (int s = 128; s > 0; s >>= 1) { if (tid < s) red[tid] += red[tid + s]; __syncthreads(); }
    if (tid == 0) { g_M[b] = M; g_Z[b] = red[0]; }
}

// ---------------------------------------------------------------------------
// K2b: partial weighted sums (64 slices of 32 rows)
// ---------------------------------------------------------------------------
__global__ void bw_part(const float* __restrict__ aud) {
    int k = blockIdx.x, b = blockIdx.y, tid = threadIdx.x;
    __shared__ float wts[32];
    __shared__ float red[256];
    float M = g_M[b];
    if (tid < 32) wts[tid] = __expf(g_m[b * CT + k * 32 + tid] - M);
    __syncthreads();
    int d = tid & 127, half = tid >> 7;
    const float* ab = aud + (size_t)(b * CT + k * 32) * CD;
    float acc = 0.f;
    #pragma unroll
    for (int i = 0; i < 16; i++) {
        int t = half * 16 + i;
        acc = fmaf(wts[t], ab[(size_t)t * CD + d], acc);
    }
    red[tid] = acc; __syncthreads();
    if (tid < 128) g_h2p[(size_t)(b * 64 + k) * CD + tid] = red[tid] + red[tid + 128];
}

// ---------------------------------------------------------------------------
// K2c: reduce partials: g_h2[b,:] = sum_k g_h2p[b,k,:] / Z
// ---------------------------------------------------------------------------
__global__ void bw_red() {
    int b = blockIdx.x, d = threadIdx.x;
    float s = 0.f;
    #pragma unroll
    for (int k = 0; k < 64; k++) s += g_h2p[(size_t)(b * 64 + k) * CD + d];
    g_h2[b * CD + d] = s / g_Z[b];
}

// ---------------------------------------------------------------------------
// K3: out[:,:,384:512] = aud * h_con_a2[b]
// ---------------------------------------------------------------------------
__global__ void out4_kernel(const float* __restrict__ aud, float* __restrict__ out) {
    int q = blockIdx.x * blockDim.x + threadIdx.x;
    int dq  = q & 31;
    int row = q >> 5;
    int b   = row >> 11;
    float4 a = reinterpret_cast<const float4*>(aud)[q];
    float4 h = reinterpret_cast<const float4*>(g_h2)[b * (CD / 4) + dq];
    float4 r;
    r.x = a.x * h.x; r.y = a.y * h.y; r.z = a.z * h.z; r.w = a.w * h.w;
    reinterpret_cast<float4*>(out)[(size_t)row * 128 + 96 + dq] = r;
}

// ---------------------------------------------------------------------------
extern "C" void kernel_launch(void* const* d_in, const int* in_sizes, int n_in,
                              void* d_out, int out_size) {
    const float* aud = (const float*)d_in[0];
    const float* sem = (const float*)d_in[1];
    const float* W   = (const float*)d_in[2];
    float* out = (float*)d_out;

    cudaFuncSetAttribute(flow_mma, cudaFuncAttributeMaxDynamicSharedMemorySize, SMEM_SZ);

    conv_kernel<<<4096, 256>>>(sem, W);
    dim3 grid(CT / BT, CB);
    flow_mma<<<grid, 128, SMEM_SZ>>>(aud, W, out);
    bw_pre<<<CB, 256>>>();
    bw_part<<<dim3(64, CB), 256>>>(aud);
    bw_red<<<CB, 128>>>();
    out4_kernel<<<(CB * CT * CD / 4) / 256, 256>>>(aud, out);
}

// round 15
// speedup vs baseline: 1.8087x; 1.8087x over previous
#include <cuda_runtime.h>
#include <cuda_fp16.h>
#include <stdint.h>

constexpr int CB = 16, CT = 2048, CN = 2048, CD = 128;
constexpr int BT = 128, BN = 64;
constexpr int NTILES = CN / BN;
constexpr float LOG2E = 1.4426950408889634f;
constexpr float LN2   = 0.6931471805599453f;

// Scratch (device globals — no allocation allowed)
__device__ float g_a2[CB * CN];     // a2 * LOG2E
__device__ float g_m [CB * CT];
__device__ float g_M [CB];
__device__ float g_Z [CB];
__device__ __align__(16) float g_h2 [CB * CD];
__device__ __align__(16) float g_h2p[CB * 64 * CD];
__device__ __align__(16) __half g_sh[CB * CN * CD];   // fp16(sem)

// ---------------- smem layout (bytes) ----------------
constexpr int OFF_A2S  = 0;                      // [2][64] f
constexpr int OFF_MSE  = 1024;                   // [128] f (m staging)
constexpr int OFF_A    = 4096;                   // f16 [128][136] stride 272 -> 34816
constexpr int OFF_B    = OFF_A + 34816;          // 2 x f16 [64][136] stride 272
constexpr int BBUF     = 17408;
constexpr int SMEM_SZ  = OFF_B + 2 * BBUF;       // 73728
constexpr int OFF_HS   = OFF_A;                  // epilogue float hs[128][132]

__device__ __forceinline__ uint32_t smem_u32(const void* p) {
    uint32_t a;
    asm("{ .reg .u64 t; cvta.to.shared.u64 t, %1; cvt.u32.u64 %0, t; }" : "=r"(a) : "l"(p));
    return a;
}
__device__ __forceinline__ void ldsm4(uint32_t* r, uint32_t a) {
    asm volatile("ldmatrix.sync.aligned.m8n8.x4.shared.b16 {%0,%1,%2,%3}, [%4];"
                 : "=r"(r[0]), "=r"(r[1]), "=r"(r[2]), "=r"(r[3]) : "r"(a));
}
__device__ __forceinline__ void ldsm4t(uint32_t* r, uint32_t a) {
    asm volatile("ldmatrix.sync.aligned.m8n8.x4.trans.shared.b16 {%0,%1,%2,%3}, [%4];"
                 : "=r"(r[0]), "=r"(r[1]), "=r"(r[2]), "=r"(r[3]) : "r"(a));
}
__device__ __forceinline__ void mma16816h(uint32_t* c, const uint32_t* a, const uint32_t* b) {
    asm volatile(
        "mma.sync.aligned.m16n8k16.row.col.f16.f16.f16.f16 "
        "{%0,%1}, {%2,%3,%4,%5}, {%6,%7}, {%0,%1};"
        : "+r"(c[0]), "+r"(c[1])
        : "r"(a[0]), "r"(a[1]), "r"(a[2]), "r"(a[3]), "r"(b[0]), "r"(b[1]));
}
__device__ __forceinline__ float ex2(float x) {
    float r;
    asm("ex2.approx.ftz.f32 %0, %1;" : "=f"(r) : "f"(x));
    return r;
}
__device__ __forceinline__ uint32_t packhf(float lo, float hi) {
    uint32_t r;
    asm("cvt.rn.f16x2.f32 %0, %1, %2;" : "=r"(r) : "f"(hi), "f"(lo));
    return r;
}
__device__ __forceinline__ float2 unpackh(uint32_t u) {
    __half2 h = *reinterpret_cast<__half2*>(&u);
    return __half22float2(h);
}
__device__ __forceinline__ void cpasync16(uint32_t saddr, const void* gaddr) {
    asm volatile("cp.async.cg.shared.global [%0], [%1], 16;" :: "r"(saddr), "l"(gaddr) : "memory");
}
__device__ __forceinline__ void cpasync_commit() {
    asm volatile("cp.async.commit_group;" ::: "memory");
}
template <int N>
__device__ __forceinline__ void cpasync_wait() {
    asm volatile("cp.async.wait_group %0;" :: "n"(N) : "memory");
}
__device__ __forceinline__ uint2 to_hf4(float4 v) {
    return make_uint2(packhf(v.x, v.y), packhf(v.z, v.w));
}

// ---------------------------------------------------------------------------
// K0: sem-only convert + prep: g_sh = fp16(sem); g_a2 = (sem.w2)*LOG2E
// ---------------------------------------------------------------------------
__global__ void conv_kernel(const float* __restrict__ sem, const float* __restrict__ W) {
    int row = (blockIdx.x * blockDim.x + threadIdx.x) >> 5;
    int lane = threadIdx.x & 31;
    const float4* f  = reinterpret_cast<const float4*>(sem) + (size_t)row * 32;
    const float4* W4 = reinterpret_cast<const float4*>(W);
    float4 x  = f[lane];
    float4 wv = W4[32 + lane];
    float s = x.x * wv.x + x.y * wv.y + x.z * wv.z + x.w * wv.w;
    #pragma unroll
    for (int o = 16; o > 0; o >>= 1) s += __shfl_xor_sync(0xffffffffu, s, o);
    if (lane == 0) g_a2[row] = s * LOG2E;
    reinterpret_cast<uint2*>(g_sh)[(size_t)row * 32 + lane] = to_hf4(x);
}

// ---------------------------------------------------------------------------
// K1: register-P flash kernel, fp16 MMA, 4 warps x 32 rows, 2 CTAs/SM.
// A built inline from fp32; a1 computed in epilogue. (R13 baseline)
// ---------------------------------------------------------------------------
__global__ void __launch_bounds__(128, 2)
flow_mma(const float* __restrict__ aud, const float* __restrict__ W,
         float* __restrict__ out) {
    extern __shared__ char smem[];
    const uint32_t sb = smem_u32(smem);
    const int tid = threadIdx.x, lane = tid & 31, w = tid >> 5;   // w in 0..3
    const int q = lane >> 2, cp = lane & 3;
    const int b = blockIdx.y, t0 = blockIdx.x * BT;

    float* a2s = (float*)(smem + OFF_A2S);
    float* mse = (float*)(smem + OFF_MSE);

    const float* audb = aud + (size_t)(b * CT + t0) * CD;
    const char* gsh0  = (const char*)(g_sh + (size_t)(b * CN) * CD);

    const int prow = tid & 63, pch = (tid >> 6) * 128;   // B: row, 128B-half

    // ---- prologue: cp.async B tile 0 and 1 ----
    #pragma unroll
    for (int cc = 0; cc < 8; cc++)
        cpasync16(sb + OFF_B + prow * 272 + pch + cc * 16,
                  gsh0 + (size_t)prow * 256 + pch + cc * 16);
    cpasync_commit();
    #pragma unroll
    for (int cc = 0; cc < 8; cc++)
        cpasync16(sb + OFF_B + BBUF + prow * 272 + pch + cc * 16,
                  gsh0 + (size_t)(BN + prow) * 256 + pch + cc * 16);
    cpasync_commit();

    // ---- A = fp16(aud*w3) built inline (own row), overlaps cp.async ----
    {
        int row = tid;
        #pragma unroll
        for (int cc = 0; cc < 32; cc++) {
            int col = cc * 4;
            float4 v  = *reinterpret_cast<const float4*>(audb + (size_t)row * CD + col);
            float4 wq = *reinterpret_cast<const float4*>(W + 2 * CD + col);
            v.x *= wq.x; v.y *= wq.y; v.z *= wq.z; v.w *= wq.w;
            *(uint2*)(smem + OFF_A + row * 272 + col * 2) = to_hf4(v);
        }
        if (tid < 64) a2s[tid] = g_a2[b * CN + tid];
    }
    cpasync_wait<1>();       // B0 landed
    __syncthreads();

    const uint32_t aBase = sb + OFF_A + (w * 32 + (lane & 15)) * 272 + ((lane >> 4) * 8) * 2;

    uint32_t Oh[2][16][2];
    #pragma unroll
    for (int mi = 0; mi < 2; mi++)
        #pragma unroll
        for (int d = 0; d < 16; d++) { Oh[mi][d][0] = 0u; Oh[mi][d][1] = 0u; }
    float lreg[2][2] = {{0.f, 0.f}, {0.f, 0.f}};
    float mreg[2][2] = {{-1e30f, -1e30f}, {-1e30f, -1e30f}};

    for (int it = 0; it < NTILES; it++) {
        const int cur = it & 1, nxt = cur ^ 1;
        const uint32_t bB = sb + OFF_B + cur * BBUF;

        // ---- GEMM1: S[32,64] = A @ B^T  (fp16 accumulate) ----
        uint32_t Sh[2][8][2];
        #pragma unroll
        for (int mi = 0; mi < 2; mi++)
            #pragma unroll
            for (int ni = 0; ni < 8; ni++) { Sh[mi][ni][0] = 0u; Sh[mi][ni][1] = 0u; }

        #pragma unroll
        for (int kk = 0; kk < 8; kk++) {
            uint32_t Afr[2][4];
            ldsm4(Afr[0], aBase + kk * 32);
            ldsm4(Afr[1], aBase + 16 * 272 + kk * 32);
            #pragma unroll
            for (int nn = 0; nn < 4; nn++) {
                uint32_t Bh[4];
                ldsm4(Bh, bB + (nn * 16 + (lane & 7) + ((lane >> 4) & 1) * 8) * 272
                          + (kk * 16 + ((lane >> 3) & 1) * 8) * 2);
                #pragma unroll
                for (int mi = 0; mi < 2; mi++) {
                    mma16816h(Sh[mi][nn * 2 + 0], Afr[mi], Bh + 0);
                    mma16816h(Sh[mi][nn * 2 + 1], Afr[mi], Bh + 2);
                }
            }
        }

        // ---- softmax: P = exp2(S*log2e + a2l) -> fp16 GEMM2 A-fragments ----
        uint32_t Pf[4][2][4];
        #pragma unroll
        for (int j = 0; j < 4; j++) {
            #pragma unroll
            for (int s = 0; s < 2; s++) {
                int ni = 2 * j + s;
                int col = ni * 8 + 2 * cp;
                float a20 = a2s[cur * 64 + col], a21 = a2s[cur * 64 + col + 1];
                #pragma unroll
                for (int mi = 0; mi < 2; mi++) {
                    float2 s01 = unpackh(Sh[mi][ni][0]);   // row q
                    float2 s23 = unpackh(Sh[mi][ni][1]);   // row q+8
                    float g0 = fmaf(s01.x, LOG2E, a20);
                    float g1 = fmaf(s01.y, LOG2E, a21);
                    float g2 = fmaf(s23.x, LOG2E, a20);
                    float g3 = fmaf(s23.y, LOG2E, a21);
                    float p0 = ex2(g0), p1 = ex2(g1), p2 = ex2(g2), p3 = ex2(g3);
                    mreg[mi][0] = fmaxf(mreg[mi][0], fmaxf(g0, g1));
                    mreg[mi][1] = fmaxf(mreg[mi][1], fmaxf(g2, g3));
                    lreg[mi][0] += p0 + p1;
                    lreg[mi][1] += p2 + p3;
                    Pf[j][mi][s * 2 + 0] = packhf(p0, p1);
                    Pf[j][mi][s * 2 + 1] = packhf(p2, p3);
                }
            }
        }

        // ---- tile it+1 resident in B[nxt] (thread-local); a2 for it+1 ----
        cpasync_wait<0>();
        if (it + 1 < NTILES && tid < 64)
            a2s[nxt * 64 + tid] = g_a2[b * CN + (it + 1) * BN + tid];

        // ---- GEMM2: O[32,128] += P @ V ----
        #pragma unroll
        for (int j = 0; j < 4; j++) {
            #pragma unroll
            for (int dd = 0; dd < 8; dd++) {
                uint32_t Vh[4];
                ldsm4t(Vh, bB + (j * 16 + (lane & 7) + ((lane >> 3) & 1) * 8) * 272
                           + (dd * 16 + (lane >> 4) * 8) * 2);
                #pragma unroll
                for (int mi = 0; mi < 2; mi++) {
                    mma16816h(Oh[mi][dd * 2 + 0], Pf[j][mi], Vh + 0);
                    mma16816h(Oh[mi][dd * 2 + 1], Pf[j][mi], Vh + 2);
                }
            }
        }
        __syncthreads();   // B[cur] free for refill; B[nxt] visible CTA-wide

        // ---- fetch tile it+2 into B[cur] ----
        if (it + 2 < NTILES) {
            const char* gsrc = gsh0 + (size_t)((it + 2) * BN + prow) * 256;
            #pragma unroll
            for (int cc = 0; cc < 8; cc++)
                cpasync16(sb + OFF_B + cur * BBUF + prow * 272 + pch + cc * 16,
                          gsrc + pch + cc * 16);
            cpasync_commit();
        }
    }

    // ---- l/m: warp-local; stage m'*ln2 in smem ----
    float inv[2][2];
    #pragma unroll
    for (int mi = 0; mi < 2; mi++)
        #pragma unroll
        for (int half = 0; half < 2; half++) {
            float ls = lreg[mi][half], lm = mreg[mi][half];
            ls += __shfl_xor_sync(0xffffffffu, ls, 1);
            ls += __shfl_xor_sync(0xffffffffu, ls, 2);
            lm = fmaxf(lm, __shfl_xor_sync(0xffffffffu, lm, 1));
            lm = fmaxf(lm, __shfl_xor_sync(0xffffffffu, lm, 2));
            inv[mi][half] = 1.0f / ls;
            if (cp == 0) mse[w * 32 + mi * 16 + q + half * 8] = lm * LN2;
        }
    __syncthreads();   // smem reads done; reuse as hs

    // ---- epilogue: h = O * (1/l), stage in smem, coalesced writes ----
    float* hs = (float*)(smem + OFF_HS);
    #pragma unroll
    for (int mi = 0; mi < 2; mi++)
        #pragma unroll
        for (int d2 = 0; d2 < 16; d2++) {
            int col = d2 * 8 + 2 * cp;
            int row0 = w * 32 + mi * 16 + q;
            float2 o01 = unpackh(Oh[mi][d2][0]);
            float2 o23 = unpackh(Oh[mi][d2][1]);
            *reinterpret_cast<float2*>(&hs[row0 * 132 + col]) =
                make_float2(o01.x * inv[mi][0], o01.y * inv[mi][0]);
            *reinterpret_cast<float2*>(&hs[(row0 + 8) * 132 + col]) =
                make_float2(o23.x * inv[mi][1], o23.y * inv[mi][1]);
        }
    __syncthreads();

    float4 wq1 = reinterpret_cast<const float4*>(W)[lane];
    #pragma unroll
    for (int e = 0; e < 32; e++) {
        int r = w + 4 * e;
        float4 a = reinterpret_cast<const float4*>(audb + (size_t)r * CD)[lane];
        float4 h = *reinterpret_cast<const float4*>(&hs[r * 132 + lane * 4]);
        float* orow = out + (size_t)(b * CT + t0 + r) * (4 * CD);
        reinterpret_cast<float4*>(orow)[lane] = a;
        reinterpret_cast<float4*>(orow + 128)[lane] = h;
        float4 m4 = make_float4(a.x * h.x, a.y * h.y, a.z * h.z, a.w * h.w);
        reinterpret_cast<float4*>(orow + 256)[lane] = m4;
        // a1[r] = aud[r].w1 (fp32 lane-reduce), g_m = m' + a1
        float part = a.x * wq1.x + a.y * wq1.y + a.z * wq1.z + a.w * wq1.w;
        #pragma unroll
        for (int o = 16; o > 0; o >>= 1) part += __shfl_xor_sync(0xffffffffu, part, o);
        if (lane == 0) g_m[b * CT + t0 + r] = mse[r] + part;
    }
}

// ---------------------------------------------------------------------------
// K2a: per batch: M = max_t m, Z = sum exp(m-M)
// ---------------------------------------------------------------------------
__global__ void bw_pre() {
    int b = blockIdx.x, tid = threadIdx.x;
    __shared__ float red[256];
    const float* mb = g_m + b * CT;
    float lm = -1e30f;
    for (int t = tid; t < CT; t += 256) lm = fmaxf(lm, mb[t]);
    red[tid] = lm; __syncthreads();
    for (int s = 128; s > 0; s >>= 1) { if (tid < s) red[tid] = fmaxf(red[tid], red[tid + s]); __syncthreads(); }
    float M = red[0]; __syncthreads();
    float ls = 0.f;
    for (int t = tid; t < CT; t += 256) ls += __expf(mb[t] - M);
    red[tid] = ls; __syncthreads();
    for (int s = 128; s > 0; s >>= 1) { if (tid < s) red[tid] += red[tid + s]; __syncthreads(); }
    if (tid == 0) { g_M[b] = M; g_Z[b] = red[0]; }
}

// ---------------------------------------------------------------------------
// K2b: partial weighted sums (64 slices of 32 rows)
// ---------------------------------------------------------------------------
__global__ void bw_part(const float* __restrict__ aud) {
    int k = blockIdx.x, b = blockIdx.y, tid = threadIdx.x;
    __shared__ float wts[32];
    __shared__ float red[256];
    float M = g_M[b];
    if (tid < 32) wts[tid] = __expf(g_m[b * CT + k * 32 + tid] - M);
    __syncthreads();
    int d = tid & 127, half = tid >> 7;
    const float* ab = aud + (size_t)(b * CT + k * 32) * CD;
    float acc = 0.f;
    #pragma unroll
    for (int i = 0; i < 16; i++) {
        int t = half * 16 + i;
        acc = fmaf(wts[t], ab[(size_t)t * CD + d], acc);
    }
    red[tid] = acc; __syncthreads();
    if (tid < 128) g_h2p[(size_t)(b * 64 + k) * CD + tid] = red[tid] + red[tid + 128];
}

// ---------------------------------------------------------------------------
// K2c: reduce partials: g_h2[b,:] = sum_k g_h2p[b,k,:] / Z
// ---------------------------------------------------------------------------
__global__ void bw_red() {
    int b = blockIdx.x, d = threadIdx.x;
    float s = 0.f;
    #pragma unroll
    for (int k = 0; k < 64; k++) s += g_h2p[(size_t)(b * 64 + k) * CD + d];
    g_h2[b * CD + d] = s / g_Z[b];
}

// ---------------------------------------------------------------------------
// K3: out[:,:,384:512] = aud * h_con_a2[b]
// ---------------------------------------------------------------------------
__global__ void out4_kernel(const float* __restrict__ aud, float* __restrict__ out) {
    int q = blockIdx.x * blockDim.x + threadIdx.x;
    int dq  = q & 31;
    int row = q >> 5;
    int b   = row >> 11;
    float4 a = reinterpret_cast<const float4*>(aud)[q];
    float4 h = reinterpret_cast<const float4*>(g_h2)[b * (CD / 4) + dq];
    float4 r;
    r.x = a.x * h.x; r.y = a.y * h.y; r.z = a.z * h.z; r.w = a.w * h.w;
    reinterpret_cast<float4*>(out)[(size_t)row * 128 + 96 + dq] = r;
}

// ---------------------------------------------------------------------------
extern "C" void kernel_launch(void* const* d_in, const int* in_sizes, int n_in,
                              void* d_out, int out_size) {
    const float* aud = (const float*)d_in[0];
    const float* sem = (const float*)d_in[1];
    const float* W   = (const float*)d_in[2];
    float* out = (float*)d_out;

    cudaFuncSetAttribute(flow_mma, cudaFuncAttributeMaxDynamicSharedMemorySize, SMEM_SZ);

    conv_kernel<<<4096, 256>>>(sem, W);
    dim3 grid(CT / BT, CB);
    flow_mma<<<grid, 128, SMEM_SZ>>>(aud, W, out);
    bw_pre<<<CB, 256>>>();
    bw_part<<<dim3(64, CB), 256>>>(aud);
    bw_red<<<CB, 128>>>();
    out4_kernel<<<(CB * CT * CD / 4) / 256, 256>>>(aud, out);
}

// round 16
// speedup vs baseline: 1.8560x; 1.0261x over previous
#include <cuda_runtime.h>
#include <cuda_fp16.h>
#include <stdint.h>

constexpr int CB = 16, CT = 2048, CN = 2048, CD = 128;
constexpr int BT = 128, BN = 64;
constexpr int NTILES = CN / BN;
constexpr float LOG2E = 1.4426950408889634f;
constexpr float LN2   = 0.6931471805599453f;

// Scratch (device globals — no allocation allowed)
__device__ float g_a2[CB * CN];     // a2 * LOG2E
__device__ float g_m [CB * CT];
__device__ __align__(16) float g_h2p[CB * 64 * CD];
__device__ __align__(16) __half g_sh[CB * CN * CD];   // fp16(sem)

// ---------------- smem layout (bytes) ----------------
constexpr int OFF_A2S  = 0;                      // [2][64] f
constexpr int OFF_MSE  = 1024;                   // [128] f (m staging)
constexpr int OFF_A    = 4096;                   // f16 [128][136] stride 272 -> 34816
constexpr int OFF_B    = OFF_A + 34816;          // 2 x f16 [64][136] stride 272
constexpr int BBUF     = 17408;
constexpr int SMEM_SZ  = OFF_B + 2 * BBUF;       // 73728
constexpr int OFF_HS   = OFF_A;                  // epilogue float hs[128][132]

__device__ __forceinline__ uint32_t smem_u32(const void* p) {
    uint32_t a;
    asm("{ .reg .u64 t; cvta.to.shared.u64 t, %1; cvt.u32.u64 %0, t; }" : "=r"(a) : "l"(p));
    return a;
}
__device__ __forceinline__ void ldsm4(uint32_t* r, uint32_t a) {
    asm volatile("ldmatrix.sync.aligned.m8n8.x4.shared.b16 {%0,%1,%2,%3}, [%4];"
                 : "=r"(r[0]), "=r"(r[1]), "=r"(r[2]), "=r"(r[3]) : "r"(a));
}
__device__ __forceinline__ void ldsm4t(uint32_t* r, uint32_t a) {
    asm volatile("ldmatrix.sync.aligned.m8n8.x4.trans.shared.b16 {%0,%1,%2,%3}, [%4];"
                 : "=r"(r[0]), "=r"(r[1]), "=r"(r[2]), "=r"(r[3]) : "r"(a));
}
__device__ __forceinline__ void mma16816h(uint32_t* c, const uint32_t* a, const uint32_t* b) {
    asm volatile(
        "mma.sync.aligned.m16n8k16.row.col.f16.f16.f16.f16 "
        "{%0,%1}, {%2,%3,%4,%5}, {%6,%7}, {%0,%1};"
        : "+r"(c[0]), "+r"(c[1])
        : "r"(a[0]), "r"(a[1]), "r"(a[2]), "r"(a[3]), "r"(b[0]), "r"(b[1]));
}
__device__ __forceinline__ float ex2(float x) {
    float r;
    asm("ex2.approx.ftz.f32 %0, %1;" : "=f"(r) : "f"(x));
    return r;
}
__device__ __forceinline__ uint32_t packhf(float lo, float hi) {
    uint32_t r;
    asm("cvt.rn.f16x2.f32 %0, %1, %2;" : "=r"(r) : "f"(hi), "f"(lo));
    return r;
}
__device__ __forceinline__ float2 unpackh(uint32_t u) {
    __half2 h = *reinterpret_cast<__half2*>(&u);
    return __half22float2(h);
}
__device__ __forceinline__ void cpasync16(uint32_t saddr, const void* gaddr) {
    asm volatile("cp.async.cg.shared.global [%0], [%1], 16;" :: "r"(saddr), "l"(gaddr) : "memory");
}
__device__ __forceinline__ void cpasync_commit() {
    asm volatile("cp.async.commit_group;" ::: "memory");
}
template <int N>
__device__ __forceinline__ void cpasync_wait() {
    asm volatile("cp.async.wait_group %0;" :: "n"(N) : "memory");
}
__device__ __forceinline__ uint2 to_hf4(float4 v) {
    return make_uint2(packhf(v.x, v.y), packhf(v.z, v.w));
}

// ---------------------------------------------------------------------------
// K0: sem-only convert + prep: g_sh = fp16(sem); g_a2 = (sem.w2)*LOG2E
// ---------------------------------------------------------------------------
__global__ void conv_kernel(const float* __restrict__ sem, const float* __restrict__ W) {
    int row = (blockIdx.x * blockDim.x + threadIdx.x) >> 5;
    int lane = threadIdx.x & 31;
    const float4* f  = reinterpret_cast<const float4*>(sem) + (size_t)row * 32;
    const float4* W4 = reinterpret_cast<const float4*>(W);
    float4 x  = f[lane];
    float4 wv = W4[32 + lane];
    float s = x.x * wv.x + x.y * wv.y + x.z * wv.z + x.w * wv.w;
    #pragma unroll
    for (int o = 16; o > 0; o >>= 1) s += __shfl_xor_sync(0xffffffffu, s, o);
    if (lane == 0) g_a2[row] = s * LOG2E;
    reinterpret_cast<uint2*>(g_sh)[(size_t)row * 32 + lane] = to_hf4(x);
}

// ---------------------------------------------------------------------------
// K1: register-P flash kernel, fp16 MMA, 4 warps x 32 rows, 2 CTAs/SM.
// A built inline from fp32; a1 computed in epilogue. (R13/R15 baseline)
// ---------------------------------------------------------------------------
__global__ void __launch_bounds__(128, 2)
flow_mma(const float* __restrict__ aud, const float* __restrict__ W,
         float* __restrict__ out) {
    extern __shared__ char smem[];
    const uint32_t sb = smem_u32(smem);
    const int tid = threadIdx.x, lane = tid & 31, w = tid >> 5;   // w in 0..3
    const int q = lane >> 2, cp = lane & 3;
    const int b = blockIdx.y, t0 = blockIdx.x * BT;

    float* a2s = (float*)(smem + OFF_A2S);
    float* mse = (float*)(smem + OFF_MSE);

    const float* audb = aud + (size_t)(b * CT + t0) * CD;
    const char* gsh0  = (const char*)(g_sh + (size_t)(b * CN) * CD);

    const int prow = tid & 63, pch = (tid >> 6) * 128;   // B: row, 128B-half

    // ---- prologue: cp.async B tile 0 and 1 ----
    #pragma unroll
    for (int cc = 0; cc < 8; cc++)
        cpasync16(sb + OFF_B + prow * 272 + pch + cc * 16,
                  gsh0 + (size_t)prow * 256 + pch + cc * 16);
    cpasync_commit();
    #pragma unroll
    for (int cc = 0; cc < 8; cc++)
        cpasync16(sb + OFF_B + BBUF + prow * 272 + pch + cc * 16,
                  gsh0 + (size_t)(BN + prow) * 256 + pch + cc * 16);
    cpasync_commit();

    // ---- A = fp16(aud*w3) built inline (own row), overlaps cp.async ----
    {
        int row = tid;
        #pragma unroll
        for (int cc = 0; cc < 32; cc++) {
            int col = cc * 4;
            float4 v  = *reinterpret_cast<const float4*>(audb + (size_t)row * CD + col);
            float4 wq = *reinterpret_cast<const float4*>(W + 2 * CD + col);
            v.x *= wq.x; v.y *= wq.y; v.z *= wq.z; v.w *= wq.w;
            *(uint2*)(smem + OFF_A + row * 272 + col * 2) = to_hf4(v);
        }
        if (tid < 64) a2s[tid] = g_a2[b * CN + tid];
    }
    cpasync_wait<1>();       // B0 landed
    __syncthreads();

    const uint32_t aBase = sb + OFF_A + (w * 32 + (lane & 15)) * 272 + ((lane >> 4) * 8) * 2;

    uint32_t Oh[2][16][2];
    #pragma unroll
    for (int mi = 0; mi < 2; mi++)
        #pragma unroll
        for (int d = 0; d < 16; d++) { Oh[mi][d][0] = 0u; Oh[mi][d][1] = 0u; }
    float lreg[2][2] = {{0.f, 0.f}, {0.f, 0.f}};
    float mreg[2][2] = {{-1e30f, -1e30f}, {-1e30f, -1e30f}};

    for (int it = 0; it < NTILES; it++) {
        const int cur = it & 1, nxt = cur ^ 1;
        const uint32_t bB = sb + OFF_B + cur * BBUF;

        // ---- GEMM1: S[32,64] = A @ B^T  (fp16 accumulate) ----
        uint32_t Sh[2][8][2];
        #pragma unroll
        for (int mi = 0; mi < 2; mi++)
            #pragma unroll
            for (int ni = 0; ni < 8; ni++) { Sh[mi][ni][0] = 0u; Sh[mi][ni][1] = 0u; }

        #pragma unroll
        for (int kk = 0; kk < 8; kk++) {
            uint32_t Afr[2][4];
            ldsm4(Afr[0], aBase + kk * 32);
            ldsm4(Afr[1], aBase + 16 * 272 + kk * 32);
            #pragma unroll
            for (int nn = 0; nn < 4; nn++) {
                uint32_t Bh[4];
                ldsm4(Bh, bB + (nn * 16 + (lane & 7) + ((lane >> 4) & 1) * 8) * 272
                          + (kk * 16 + ((lane >> 3) & 1) * 8) * 2);
                #pragma unroll
                for (int mi = 0; mi < 2; mi++) {
                    mma16816h(Sh[mi][nn * 2 + 0], Afr[mi], Bh + 0);
                    mma16816h(Sh[mi][nn * 2 + 1], Afr[mi], Bh + 2);
                }
            }
        }

        // ---- softmax: P = exp2(S*log2e + a2l) -> fp16 GEMM2 A-fragments ----
        uint32_t Pf[4][2][4];
        #pragma unroll
        for (int j = 0; j < 4; j++) {
            #pragma unroll
            for (int s = 0; s < 2; s++) {
                int ni = 2 * j + s;
                int col = ni * 8 + 2 * cp;
                float a20 = a2s[cur * 64 + col], a21 = a2s[cur * 64 + col + 1];
                #pragma unroll
                for (int mi = 0; mi < 2; mi++) {
                    float2 s01 = unpackh(Sh[mi][ni][0]);   // row q
                    float2 s23 = unpackh(Sh[mi][ni][1]);   // row q+8
                    float g0 = fmaf(s01.x, LOG2E, a20);
                    float g1 = fmaf(s01.y, LOG2E, a21);
                    float g2 = fmaf(s23.x, LOG2E, a20);
                    float g3 = fmaf(s23.y, LOG2E, a21);
                    float p0 = ex2(g0), p1 = ex2(g1), p2 = ex2(g2), p3 = ex2(g3);
                    mreg[mi][0] = fmaxf(mreg[mi][0], fmaxf(g0, g1));
                    mreg[mi][1] = fmaxf(mreg[mi][1], fmaxf(g2, g3));
                    lreg[mi][0] += p0 + p1;
                    lreg[mi][1] += p2 + p3;
                    Pf[j][mi][s * 2 + 0] = packhf(p0, p1);
                    Pf[j][mi][s * 2 + 1] = packhf(p2, p3);
                }
            }
        }

        // ---- tile it+1 resident in B[nxt] (thread-local); a2 for it+1 ----
        cpasync_wait<0>();
        if (it + 1 < NTILES && tid < 64)
            a2s[nxt * 64 + tid] = g_a2[b * CN + (it + 1) * BN + tid];

        // ---- GEMM2: O[32,128] += P @ V ----
        #pragma unroll
        for (int j = 0; j < 4; j++) {
            #pragma unroll
            for (int dd = 0; dd < 8; dd++) {
                uint32_t Vh[4];
                ldsm4t(Vh, bB + (j * 16 + (lane & 7) + ((lane >> 3) & 1) * 8) * 272
                           + (dd * 16 + (lane >> 4) * 8) * 2);
                #pragma unroll
                for (int mi = 0; mi < 2; mi++) {
                    mma16816h(Oh[mi][dd * 2 + 0], Pf[j][mi], Vh + 0);
                    mma16816h(Oh[mi][dd * 2 + 1], Pf[j][mi], Vh + 2);
                }
            }
        }
        __syncthreads();   // B[cur] free for refill; B[nxt] visible CTA-wide

        // ---- fetch tile it+2 into B[cur] ----
        if (it + 2 < NTILES) {
            const char* gsrc = gsh0 + (size_t)((it + 2) * BN + prow) * 256;
            #pragma unroll
            for (int cc = 0; cc < 8; cc++)
                cpasync16(sb + OFF_B + cur * BBUF + prow * 272 + pch + cc * 16,
                          gsrc + pch + cc * 16);
            cpasync_commit();
        }
    }

    // ---- l/m: warp-local; stage m'*ln2 in smem ----
    float inv[2][2];
    #pragma unroll
    for (int mi = 0; mi < 2; mi++)
        #pragma unroll
        for (int half = 0; half < 2; half++) {
            float ls = lreg[mi][half], lm = mreg[mi][half];
            ls += __shfl_xor_sync(0xffffffffu, ls, 1);
            ls += __shfl_xor_sync(0xffffffffu, ls, 2);
            lm = fmaxf(lm, __shfl_xor_sync(0xffffffffu, lm, 1));
            lm = fmaxf(lm, __shfl_xor_sync(0xffffffffu, lm, 2));
            inv[mi][half] = 1.0f / ls;
            if (cp == 0) mse[w * 32 + mi * 16 + q + half * 8] = lm * LN2;
        }
    __syncthreads();   // smem reads done; reuse as hs

    // ---- epilogue: h = O * (1/l), stage in smem, coalesced writes ----
    float* hs = (float*)(smem + OFF_HS);
    #pragma unroll
    for (int mi = 0; mi < 2; mi++)
        #pragma unroll
        for (int d2 = 0; d2 < 16; d2++) {
            int col = d2 * 8 + 2 * cp;
            int row0 = w * 32 + mi * 16 + q;
            float2 o01 = unpackh(Oh[mi][d2][0]);
            float2 o23 = unpackh(Oh[mi][d2][1]);
            *reinterpret_cast<float2*>(&hs[row0 * 132 + col]) =
                make_float2(o01.x * inv[mi][0], o01.y * inv[mi][0]);
            *reinterpret_cast<float2*>(&hs[(row0 + 8) * 132 + col]) =
                make_float2(o23.x * inv[mi][1], o23.y * inv[mi][1]);
        }
    __syncthreads();

    float4 wq1 = reinterpret_cast<const float4*>(W)[lane];
    #pragma unroll
    for (int e = 0; e < 32; e++) {
        int r = w + 4 * e;
        float4 a = reinterpret_cast<const float4*>(audb + (size_t)r * CD)[lane];
        float4 h = *reinterpret_cast<const float4*>(&hs[r * 132 + lane * 4]);
        float* orow = out + (size_t)(b * CT + t0 + r) * (4 * CD);
        reinterpret_cast<float4*>(orow)[lane] = a;
        reinterpret_cast<float4*>(orow + 128)[lane] = h;
        float4 m4 = make_float4(a.x * h.x, a.y * h.y, a.z * h.z, a.w * h.w);
        reinterpret_cast<float4*>(orow + 256)[lane] = m4;
        // a1[r] = aud[r].w1 (fp32 lane-reduce), g_m = m' + a1
        float part = a.x * wq1.x + a.y * wq1.y + a.z * wq1.z + a.w * wq1.w;
        #pragma unroll
        for (int o = 16; o > 0; o >>= 1) part += __shfl_xor_sync(0xffffffffu, part, o);
        if (lane == 0) g_m[b * CT + t0 + r] = mse[r] + part;
    }
}

// ---------------------------------------------------------------------------
// K2: partial weighted sums (64 slices of 32 rows); M computed inline
// ---------------------------------------------------------------------------
__global__ void bw_part(const float* __restrict__ aud) {
    int k = blockIdx.x, b = blockIdx.y, tid = threadIdx.x;
    __shared__ float red[256];
    __shared__ float wts[32];
    const float* mb = g_m + b * CT;
    float lm = -1e30f;
    for (int t = tid; t < CT; t += 256) lm = fmaxf(lm, mb[t]);
    red[tid] = lm; __syncthreads();
    for (int s = 128; s > 0; s >>= 1) { if (tid < s) red[tid] = fmaxf(red[tid], red[tid + s]); __syncthreads(); }
    float M = red[0]; __syncthreads();
    if (tid < 32) wts[tid] = __expf(mb[k * 32 + tid] - M);
    __syncthreads();
    int d = tid & 127, half = tid >> 7;
    const float* ab = aud + (size_t)(b * CT + k * 32) * CD;
    float acc = 0.f;
    #pragma unroll
    for (int i = 0; i < 16; i++) {
        int t = half * 16 + i;
        acc = fmaf(wts[t], ab[(size_t)t * CD + d], acc);
    }
    red[tid] = acc; __syncthreads();
    if (tid < 128) g_h2p[(size_t)(b * 64 + k) * CD + tid] = red[tid] + red[tid + 128];
}

// ---------------------------------------------------------------------------
// K3: fused h2-reduce + block-4 write. Block (c,b): rows [c*128, c*128+128).
//   M, Z computed inline; h2 = (sum_k partials)/Z in smem; then stream.
// ---------------------------------------------------------------------------
__global__ void out4_kernel(const float* __restrict__ aud, float* __restrict__ out) {
    int c = blockIdx.x, b = blockIdx.y, tid = threadIdx.x;
    __shared__ float red[256];
    __shared__ __align__(16) float h2s[128];
    const float* mb = g_m + b * CT;
    float lm = -1e30f;
    for (int t = tid; t < CT; t += 256) lm = fmaxf(lm, mb[t]);
    red[tid] = lm; __syncthreads();
    for (int s = 128; s > 0; s >>= 1) { if (tid < s) red[tid] = fmaxf(red[tid], red[tid + s]); __syncthreads(); }
    float M = red[0]; __syncthreads();
    float ls = 0.f;
    for (int t = tid; t < CT; t += 256) ls += __expf(mb[t] - M);
    red[tid] = ls; __syncthreads();
    for (int s = 128; s > 0; s >>= 1) { if (tid < s) red[tid] += red[tid + s]; __syncthreads(); }
    float Z = red[0]; __syncthreads();

    int d = tid & 127, half = tid >> 7;
    float acc = 0.f;
    for (int k = half * 32; k < half * 32 + 32; k++)
        acc += g_h2p[(size_t)(b * 64 + k) * CD + d];
    red[tid] = acc; __syncthreads();
    if (tid < 128) h2s[tid] = (red[tid] + red[tid + 128]) / Z;
    __syncthreads();

    const float* ab = aud + (size_t)(b * CT + c * 128) * CD;
    float* ob = out + (size_t)(b * CT + c * 128) * (4 * CD);
    #pragma unroll
    for (int it = 0; it < 16; it++) {
        int idx = it * 256 + tid;        // 0..4095 = 128 rows x 32 quads
        int r = idx >> 5, dq = idx & 31;
        float4 a = reinterpret_cast<const float4*>(ab + (size_t)r * CD)[dq];
        float4 h = *reinterpret_cast<const float4*>(&h2s[dq * 4]);
        float4 v = make_float4(a.x * h.x, a.y * h.y, a.z * h.z, a.w * h.w);
        reinterpret_cast<float4*>(ob + (size_t)r * (4 * CD) + 3 * CD)[dq] = v;
    }
}

// ---------------------------------------------------------------------------
extern "C" void kernel_launch(void* const* d_in, const int* in_sizes, int n_in,
                              void* d_out, int out_size) {
    const float* aud = (const float*)d_in[0];
    const float* sem = (const float*)d_in[1];
    const float* W   = (const float*)d_in[2];
    float* out = (float*)d_out;

    cudaFuncSetAttribute(flow_mma, cudaFuncAttributeMaxDynamicSharedMemorySize, SMEM_SZ);

    conv_kernel<<<4096, 256>>>(sem, W);
    dim3 grid(CT / BT, CB);
    flow_mma<<<grid, 128, SMEM_SZ>>>(aud, W, out);
    bw_part<<<dim3(64, CB), 256>>>(aud);
    out4_kernel<<<dim3(16, CB), 256>>>(aud, out);
}